// round 2
// baseline (speedup 1.0000x reference)
#include <cuda_runtime.h>
#include <cuda_bf16.h>
#include <math.h>

#define KC 64
#define DD 128
#define NN 4096
#define NB 16

#define LN2F 0.6931471805599453f
#define LOG2PIF 1.8378770664093453f   // log(2*pi)

// ---------------- device scratch (no allocations allowed) ----------------
__device__ float g_mus[KC * DD];     // normalized mus, row-major [k][d]
__device__ float g_musT[DD * KC];    // transposed [d][k]
__device__ float g_kappas[KC];
__device__ float g_logC[KC];
__device__ float g_A[KC];
__device__ float g_sums[KC * DD];    // class sums of normalized features
__device__ float g_counts[KC];
__device__ float g_numer[KC * KC];   // numer_pi
__device__ float g_rank;
__device__ float g_js;
__device__ int   g_is64;             // 1 if labels buffer is int64, else int32

// ---------------- K0: zero scratch ----------------
__global__ void k_zero() {
    int idx = blockIdx.x * blockDim.x + threadIdx.x;
    int stride = gridDim.x * blockDim.x;
    for (int i = idx; i < KC * DD; i += stride) g_sums[i] = 0.0f;
    for (int i = idx; i < KC * KC; i += stride) g_numer[i] = 0.0f;
    for (int i = idx; i < KC; i += stride) g_counts[i] = 0.0f;
    if (idx == 0) { g_rank = 0.0f; g_js = 0.0f; g_is64 = 1; }
}

// ---------------- K0b: detect labels dtype ----------------
// Scan first 4096 int32 words (never OOB for either dtype). If the buffer is
// int64 (values < 64), every odd word is 0. If int32, odd words are real
// labels — the chance all 2048 are zero is negligible.
__global__ void k_detect(const int* __restrict__ labels32) {
    int idx = blockIdx.x * blockDim.x + threadIdx.x;   // 0..2047
    if (labels32[2 * idx + 1] != 0) g_is64 = 0;
}

// ---------------- K1: normalize mus, compute kappa/logC/A ----------------
__global__ void k_prep(const float* __restrict__ mus_param,
                       const float* __restrict__ rho_kappa) {
    int i = blockIdx.x;          // class
    int t = threadIdx.x;         // 0..127 = d
    __shared__ float red[DD];
    float v = mus_param[i * DD + t];
    red[t] = v * v;
    __syncthreads();
    for (int s = 64; s > 0; s >>= 1) {
        if (t < s) red[t] += red[t + s];
        __syncthreads();
    }
    float inv = 1.0f / fmaxf(sqrtf(red[0]), 1e-12f);
    float mu = v * inv;
    g_mus[i * DD + t] = mu;
    g_musT[t * KC + i] = mu;
    if (t == 0) {
        float r = rho_kappa[i];
        // stable softplus
        float kap = (r > 0.0f) ? (r + log1pf(expf(-r))) : log1pf(expf(r));
        kap = fmaxf(kap, 1e-6f);
        g_kappas[i] = kap;
        const float vnu = 63.0f;      // d/2 - 1
        const float half_d = 64.0f;
        float logI;
        if (kap < 1e-3f) {
            logI = vnu * logf(kap * 0.5f + 1e-12f) - lgammaf(vnu + 1.0f);
        } else {
            logI = kap - 0.5f * logf(2.0f * 3.14159265358979323846f * kap + 1e-12f);
        }
        g_logC[i] = -vnu * logf(kap + 1e-12f) - half_d * LOG2PIF - logI;
        float kc = fmaxf(kap, 1e-8f);
        g_A[i] = (kc > 50.0f) ? (1.0f - 127.0f / (2.0f * kc)) : (kc / 128.0f);
    }
}

// ---------------- K2: fused main — normalize features, class sums, L, numer ----------------
__global__ void __launch_bounds__(128) k_main(const float* __restrict__ feat,
                                              const int* __restrict__ labels32) {
    __shared__ float f[NB][DD];      // raw features
    __shared__ float invn[NB];
    __shared__ float Lsh[NB][KC];
    __shared__ int lab[NB];
    int tid = threadIdx.x;
    int n0 = blockIdx.x * NB;

    // load 16x128 features, coalesced
    for (int idx = tid; idx < NB * DD; idx += 128)
        f[idx >> 7][idx & 127] = feat[n0 * DD + idx];
    if (tid < NB) {
        int shift = g_is64 ? 1 : 0;
        int l = labels32[(n0 + tid) << shift];
        lab[tid] = min(max(l, 0), KC - 1);
    }
    __syncthreads();

    // row norms: warp w handles rows w, w+4, w+8, w+12
    int w = tid >> 5, lane = tid & 31;
    for (int r = w; r < NB; r += 4) {
        float s = 0.0f;
#pragma unroll
        for (int c = 0; c < 4; c++) {
            float x = f[r][lane + 32 * c];
            s += x * x;
        }
#pragma unroll
        for (int o = 16; o > 0; o >>= 1) s += __shfl_xor_sync(0xffffffffu, s, o);
        if (lane == 0) invn[r] = 1.0f / fmaxf(sqrtf(s), 1e-12f);
    }
    __syncthreads();

    // class sums (normalized features) + counts
#pragma unroll
    for (int n = 0; n < NB; n++)
        atomicAdd(&g_sums[lab[n] * DD + tid], f[n][tid] * invn[n]);
    if (tid < NB) atomicAdd(&g_counts[lab[tid]], 1.0f);

    // L = logC[k] + kappa[k] * invn[n] * (f_n . mu_k); 8 samples per thread
    int g = tid >> 6;        // sample group 0/1
    int k = tid & 63;        // class index
    float acc[8];
#pragma unroll
    for (int nn = 0; nn < 8; nn++) acc[nn] = 0.0f;
    const float* fg = &f[g * 8][0];
    for (int d = 0; d < DD; d++) {
        float m = g_musT[d * KC + k];       // coalesced, L1-resident
#pragma unroll
        for (int nn = 0; nn < 8; nn++)
            acc[nn] += m * fg[nn * DD + d]; // LDS broadcast
    }
    float kap = g_kappas[k], lc = g_logC[k];
#pragma unroll
    for (int nn = 0; nn < 8; nn++) {
        int n = g * 8 + nn;
        Lsh[n][k] = lc + kap * invn[n] * acc[nn];
    }
    __syncthreads();

    // numer_pi[label_n][k] += ln2 - softplus(L[n,k] - L[n,label_n])
#pragma unroll
    for (int nn = 0; nn < 8; nn++) {
        int n = g * 8 + nn;
        float Li = Lsh[n][lab[n]];
        float x = Lsh[n][k] - Li;
        float sp = (x > 0.0f) ? (x + log1pf(expf(-x))) : log1pf(expf(x));
        atomicAdd(&g_numer[lab[n] * KC + k], LN2F - sp);
    }
}

// ---------------- K3: rank loss ----------------
__global__ void k_rank() {
    int i = blockIdx.x;       // row class
    int j = threadIdx.x;      // col class (64 threads)
    __shared__ float mean_sh[DD];
    __shared__ float red[KC];
    __shared__ float diag_sh;
    float cnt = g_counts[i];
    bool zi = (cnt == 0.0f);
    float cs = fmaxf(cnt, 1.0f);
    for (int d = j; d < DD; d += KC)
        mean_sh[d] = zi ? g_mus[i * DD + d] : (g_sums[i * DD + d] / cs);
    __syncthreads();
    float dot = 0.0f;
    for (int d = 0; d < DD; d++)
        dot += mean_sh[d] * g_musT[d * KC + j];
    if (j == i) diag_sh = dot;
    __syncthreads();
    float Esi = g_kappas[i] * diag_sh;
    float diff = Esi - g_kappas[j] * dot;
    float h = 0.0f;
    if (j != i)
        h = fmaxf(0.5f * fabsf((float)(i - j)) - diff, 0.0f) / cs;
    red[j] = h;
    __syncthreads();
    for (int s = 32; s > 0; s >>= 1) {
        if (j < s) red[j] += red[j + s];
        __syncthreads();
    }
    if (j == 0) atomicAdd(&g_rank, red[0]);
}

// ---------------- K4: js loss ----------------
__global__ void k_js() {
    int i = blockIdx.x;
    int j = threadIdx.x;      // 64 threads
    __shared__ float mui[DD];
    __shared__ float red[KC];
    for (int d = j; d < DD; d += KC) mui[d] = g_mus[i * DD + d];
    __syncthreads();
    float cnt_i = g_counts[i], cnt_j = g_counts[j];
    bool zp = (cnt_i == 0.0f) || (cnt_j == 0.0f);
    float js;
    if (zp) {
        float m = 0.0f;
        for (int d = 0; d < DD; d++) m += mui[d] * g_musT[d * KC + j];
        float ki = g_kappas[i], kj = g_kappas[j];
        js = 0.5f * (g_A[i] * (ki - kj * m) + g_A[j] * (kj - ki * m));
    } else {
        js = 0.5f * (g_numer[i * KC + j] / fmaxf(cnt_i, 1.0f) +
                     g_numer[j * KC + i] / fmaxf(cnt_j, 1.0f));
    }
    float wgt = (i == j) ? 0.0f : fabsf((float)(i - j));
    red[j] = wgt * js;
    __syncthreads();
    for (int s = 32; s > 0; s >>= 1) {
        if (j < s) red[j] += red[j + s];
        __syncthreads();
    }
    if (j == 0) atomicAdd(&g_js, red[0]);
}

// ---------------- K5: final combine ----------------
__global__ void k_final(float* out) {
    // sum_{i!=j} |i-j| for K=64 is 87360 (compile-time constant)
    out[0] = g_rank / (4096.0f + 1e-9f) + g_js / (87360.0f + 1e-9f);
}

extern "C" void kernel_launch(void* const* d_in, const int* in_sizes, int n_in,
                              void* d_out, int out_size) {
    const float* features  = (const float*)d_in[0];
    const float* mus_param = (const float*)d_in[1];
    const float* rho_kappa = (const float*)d_in[2];
    const int*   labels32  = (const int*)d_in[3];
    float* out = (float*)d_out;

    k_zero<<<32, 256>>>();
    k_detect<<<8, 256>>>(labels32);
    k_prep<<<KC, DD>>>(mus_param, rho_kappa);
    k_main<<<NN / NB, 128>>>(features, labels32);
    k_rank<<<KC, KC>>>();
    k_js<<<KC, KC>>>();
    k_final<<<1, 1>>>(out);
}

// round 3
// speedup vs baseline: 1.6032x; 1.6032x over previous
#include <cuda_runtime.h>
#include <cuda_bf16.h>
#include <math.h>

#define KC 64
#define DD 128
#define NN 4096
#define NB 16

#define LN2F 0.6931471805599453f
#define LOG2PIF 1.8378770664093453f   // log(2*pi)

// ---------------- device scratch (no allocations allowed) ----------------
__device__ float g_mus[KC * DD];                      // normalized mus [k][d]
__device__ __align__(16) float g_musT[DD * KC];       // transposed [d][k]
__device__ float g_kappas[KC];
__device__ float g_logC[KC];
__device__ float g_A[KC];
__device__ float g_sums[KC * DD];                     // class sums
__device__ float g_counts[KC];
__device__ float g_numer[KC * KC];                    // numer_pi
__device__ float g_rank;
__device__ float g_js;
__device__ int   g_is64;                              // labels dtype flag
__device__ int   g_done;                              // block completion counter

// ---------------- K0: zero scratch ----------------
__global__ void k_zero() {
    int idx = blockIdx.x * blockDim.x + threadIdx.x;
    int stride = gridDim.x * blockDim.x;
    for (int i = idx; i < KC * DD; i += stride) g_sums[i] = 0.0f;
    for (int i = idx; i < KC * KC; i += stride) g_numer[i] = 0.0f;
    for (int i = idx; i < KC; i += stride) g_counts[i] = 0.0f;
    if (idx == 0) { g_rank = 0.0f; g_js = 0.0f; g_is64 = 1; g_done = 0; }
}

// ---------------- K1: normalize mus, kappa/logC/A, + labels dtype detect ----------------
__global__ void k_prep(const float* __restrict__ mus_param,
                       const float* __restrict__ rho_kappa,
                       const int* __restrict__ labels32) {
    int i = blockIdx.x;          // class
    int t = threadIdx.x;         // 0..127 = d

    // labels dtype detection: if any odd int32 word in first 4096 words is
    // nonzero, the buffer is int32 (labels < 64 => int64 high words are 0).
    int gid = i * DD + t;        // 0..8191
    if (gid < 2048 && labels32[2 * gid + 1] != 0) g_is64 = 0;

    __shared__ float red[DD];
    float v = mus_param[i * DD + t];
    red[t] = v * v;
    __syncthreads();
    for (int s = 64; s > 0; s >>= 1) {
        if (t < s) red[t] += red[t + s];
        __syncthreads();
    }
    float inv = 1.0f / fmaxf(sqrtf(red[0]), 1e-12f);
    float mu = v * inv;
    g_mus[i * DD + t] = mu;
    g_musT[t * KC + i] = mu;
    if (t == 0) {
        float r = rho_kappa[i];
        float kap = (r > 0.0f) ? (r + log1pf(expf(-r))) : log1pf(expf(r));
        kap = fmaxf(kap, 1e-6f);
        g_kappas[i] = kap;
        const float vnu = 63.0f;      // d/2 - 1
        const float half_d = 64.0f;
        float logI;
        if (kap < 1e-3f) {
            logI = vnu * logf(kap * 0.5f + 1e-12f) - lgammaf(vnu + 1.0f);
        } else {
            logI = kap - 0.5f * logf(2.0f * 3.14159265358979323846f * kap + 1e-12f);
        }
        g_logC[i] = -vnu * logf(kap + 1e-12f) - half_d * LOG2PIF - logI;
        float kc = fmaxf(kap, 1e-8f);
        g_A[i] = (kc > 50.0f) ? (1.0f - 127.0f / (2.0f * kc)) : (kc / 128.0f);
    }
}

// ---------------- K2: fused main ----------------
// 256 threads, NB=16 samples per block, 4 groups of 64 k-threads, 4 samples each.
__global__ void __launch_bounds__(256) k_main(const float* __restrict__ feat,
                                              const int* __restrict__ labels32) {
    __shared__ __align__(16) float f[NB][DD];       // 8KB
    __shared__ __align__(16) float musT_sh[DD * KC]; // 32KB
    __shared__ float Lsh[NB][KC];                    // 4KB
    __shared__ float invn[NB];
    __shared__ int lab[NB];
    int tid = threadIdx.x;
    int n0 = blockIdx.x * NB;

    // load 16x128 features as float4 (512 vecs / 256 threads = 2 each)
    {
        const float4* src = (const float4*)(feat + n0 * DD);
        float4* dst = (float4*)&f[0][0];
        dst[tid]       = src[tid];
        dst[tid + 256] = src[tid + 256];
    }
    // copy musT (2048 float4 / 256 threads = 8 each)
    {
        const float4* src = (const float4*)g_musT;
        float4* dst = (float4*)musT_sh;
#pragma unroll
        for (int r = 0; r < 8; r++)
            dst[tid + 256 * r] = src[tid + 256 * r];
    }
    if (tid < NB) {
        int shift = g_is64 ? 1 : 0;
        int l = labels32[(n0 + tid) << shift];
        lab[tid] = min(max(l, 0), KC - 1);
    }
    __syncthreads();

    // row norms: warp w handles rows 2w, 2w+1
    int w = tid >> 5, lane = tid & 31;
#pragma unroll
    for (int rr = 0; rr < 2; rr++) {
        int r = 2 * w + rr;
        float s = 0.0f;
#pragma unroll
        for (int c = 0; c < 4; c++) {
            float x = f[r][lane + 32 * c];
            s += x * x;
        }
#pragma unroll
        for (int o = 16; o > 0; o >>= 1) s += __shfl_xor_sync(0xffffffffu, s, o);
        if (lane == 0) invn[r] = 1.0f / fmaxf(sqrtf(s), 1e-12f);
    }
    __syncthreads();

    // class sums: d = tid&127, half handles 8 samples
    {
        int d = tid & 127, half = tid >> 7;
#pragma unroll
        for (int nn = 0; nn < 8; nn++) {
            int n = half * 8 + nn;
            atomicAdd(&g_sums[lab[n] * DD + d], f[n][d] * invn[n]);
        }
    }
    if (tid < NB) atomicAdd(&g_counts[lab[tid]], 1.0f);

    // L = logC[k] + kappa[k] * invn[n] * (f_n . mu_k); 4 samples per thread
    int g = tid >> 6;        // sample group 0..3
    int k = tid & 63;        // class index
    float acc0 = 0.f, acc1 = 0.f, acc2 = 0.f, acc3 = 0.f;
    const float4* f0 = (const float4*)&f[g * 4 + 0][0];
    const float4* f1 = (const float4*)&f[g * 4 + 1][0];
    const float4* f2 = (const float4*)&f[g * 4 + 2][0];
    const float4* f3 = (const float4*)&f[g * 4 + 3][0];
#pragma unroll
    for (int d4 = 0; d4 < DD / 4; d4++) {
        float m0 = musT_sh[(4 * d4 + 0) * KC + k];
        float m1 = musT_sh[(4 * d4 + 1) * KC + k];
        float m2 = musT_sh[(4 * d4 + 2) * KC + k];
        float m3 = musT_sh[(4 * d4 + 3) * KC + k];
        float4 x0 = f0[d4], x1 = f1[d4], x2 = f2[d4], x3 = f3[d4];
        acc0 += m0 * x0.x + m1 * x0.y + m2 * x0.z + m3 * x0.w;
        acc1 += m0 * x1.x + m1 * x1.y + m2 * x1.z + m3 * x1.w;
        acc2 += m0 * x2.x + m1 * x2.y + m2 * x2.z + m3 * x2.w;
        acc3 += m0 * x3.x + m1 * x3.y + m2 * x3.z + m3 * x3.w;
    }
    float kap = g_kappas[k], lc = g_logC[k];
    Lsh[g * 4 + 0][k] = lc + kap * invn[g * 4 + 0] * acc0;
    Lsh[g * 4 + 1][k] = lc + kap * invn[g * 4 + 1] * acc1;
    Lsh[g * 4 + 2][k] = lc + kap * invn[g * 4 + 2] * acc2;
    Lsh[g * 4 + 3][k] = lc + kap * invn[g * 4 + 3] * acc3;
    __syncthreads();

    // numer_pi[label_n][k] += ln2 - softplus(L[n,k] - L[n,label_n])
#pragma unroll
    for (int nn = 0; nn < 4; nn++) {
        int n = g * 4 + nn;
        float Li = Lsh[n][lab[n]];
        float x = Lsh[n][k] - Li;
        float sp = (x > 0.0f) ? (x + log1pf(expf(-x))) : log1pf(expf(x));
        atomicAdd(&g_numer[lab[n] * KC + k], LN2F - sp);
    }
}

// ---------------- K3: rank + js + final combine ----------------
__global__ void k_rankjs(float* __restrict__ out) {
    int i = blockIdx.x;       // row class
    int j = threadIdx.x;      // col class (64 threads)
    __shared__ float mean_sh[DD];
    __shared__ float mui[DD];
    __shared__ float redr[KC];
    __shared__ float redj[KC];
    __shared__ float diag_sh;
    float cnt_i = g_counts[i];
    bool zi = (cnt_i == 0.0f);
    float cs = fmaxf(cnt_i, 1.0f);
    for (int d = j; d < DD; d += KC) {
        float mu = g_mus[i * DD + d];
        mui[d] = mu;
        mean_sh[d] = zi ? mu : (g_sums[i * DD + d] / cs);
    }
    __syncthreads();
    float dotm = 0.0f, dotmu = 0.0f;
    for (int d = 0; d < DD; d++) {
        float mj = g_musT[d * KC + j];
        dotm += mean_sh[d] * mj;
        dotmu += mui[d] * mj;
    }
    if (j == i) diag_sh = dotm;
    __syncthreads();
    // rank
    float diff = g_kappas[i] * diag_sh - g_kappas[j] * dotm;
    float h = (j != i) ? fmaxf(0.5f * fabsf((float)(i - j)) - diff, 0.0f) / cs : 0.0f;
    // js
    float cnt_j = g_counts[j];
    bool zp = zi || (cnt_j == 0.0f);
    float js;
    if (zp) {
        float ki = g_kappas[i], kj = g_kappas[j];
        js = 0.5f * (g_A[i] * (ki - kj * dotmu) + g_A[j] * (kj - ki * dotmu));
    } else {
        js = 0.5f * (g_numer[i * KC + j] / fmaxf(cnt_i, 1.0f) +
                     g_numer[j * KC + i] / fmaxf(cnt_j, 1.0f));
    }
    float wgt = (i == j) ? 0.0f : fabsf((float)(i - j));
    redr[j] = h;
    redj[j] = wgt * js;
    __syncthreads();
    for (int s = 32; s > 0; s >>= 1) {
        if (j < s) { redr[j] += redr[j + s]; redj[j] += redj[j + s]; }
        __syncthreads();
    }
    if (j == 0) {
        atomicAdd(&g_rank, redr[0]);
        atomicAdd(&g_js, redj[0]);
        __threadfence();
        int done = atomicAdd(&g_done, 1);
        if (done == KC - 1) {
            float r = atomicAdd(&g_rank, 0.0f);   // atomic read, fully visible
            float s = atomicAdd(&g_js, 0.0f);
            out[0] = r / (4096.0f + 1e-9f) + s / (87360.0f + 1e-9f);
        }
    }
}

extern "C" void kernel_launch(void* const* d_in, const int* in_sizes, int n_in,
                              void* d_out, int out_size) {
    const float* features  = (const float*)d_in[0];
    const float* mus_param = (const float*)d_in[1];
    const float* rho_kappa = (const float*)d_in[2];
    const int*   labels32  = (const int*)d_in[3];
    float* out = (float*)d_out;

    k_zero<<<32, 256>>>();
    k_prep<<<KC, DD>>>(mus_param, rho_kappa, labels32);
    k_main<<<NN / NB, 256>>>(features, labels32);
    k_rankjs<<<KC, KC>>>(out);
}

// round 4
// speedup vs baseline: 1.8383x; 1.1467x over previous
#include <cuda_runtime.h>
#include <cuda_bf16.h>
#include <math.h>

#define KC 64
#define DD 128
#define NN 4096
#define NB 16

#define LN2F 0.6931471805599453f
#define LOG2PIF 1.8378770664093453f   // log(2*pi)

// ---------------- device scratch (no allocations allowed) ----------------
__device__ float g_mus[KC * DD];                      // normalized mus [k][d]
__device__ __align__(16) float g_musT[DD * KC];       // transposed [d][k]
__device__ float g_kappas[KC];
__device__ float g_logC[KC];
__device__ float g_A[KC];
__device__ float g_sums[KC * DD];                     // class sums
__device__ float g_counts[KC];
__device__ float g_numer[KC * KC];                    // numer_pi
__device__ float g_rank;                              // reset by last rankjs block
__device__ float g_js;                                // reset by last rankjs block
__device__ int   g_done;                              // reset by last rankjs block
__device__ int   g_not64;                             // sticky: 1 if labels are int32

// ---------------- K1: zero scratch + normalize mus + kappa/logC/A + dtype detect ----------------
__global__ void k_prep(const float* __restrict__ mus_param,
                       const float* __restrict__ rho_kappa,
                       const int* __restrict__ labels32) {
    int i = blockIdx.x;          // class
    int t = threadIdx.x;         // 0..127 = d

    // zero accumulators (grid exactly covers them)
    g_sums[i * DD + t] = 0.0f;
    if (t < KC) g_numer[i * KC + t] = 0.0f;
    if (t == 0) g_counts[i] = 0.0f;

    // labels dtype detection (sticky flag, statically 0): if any odd int32
    // word in the first 4096 words is nonzero, the buffer is int32.
    int gid = i * DD + t;        // 0..8191
    if (gid < 2048 && labels32[2 * gid + 1] != 0) g_not64 = 1;

    __shared__ float red[DD];
    float v = mus_param[i * DD + t];
    red[t] = v * v;
    __syncthreads();
    for (int s = 64; s > 0; s >>= 1) {
        if (t < s) red[t] += red[t + s];
        __syncthreads();
    }
    float inv = 1.0f / fmaxf(sqrtf(red[0]), 1e-12f);
    float mu = v * inv;
    g_mus[i * DD + t] = mu;
    g_musT[t * KC + i] = mu;
    if (t == 0) {
        float r = rho_kappa[i];
        float kap = (r > 0.0f) ? (r + log1pf(expf(-r))) : log1pf(expf(r));
        kap = fmaxf(kap, 1e-6f);
        g_kappas[i] = kap;
        const float vnu = 63.0f;      // d/2 - 1
        const float half_d = 64.0f;
        float logI;
        if (kap < 1e-3f) {
            logI = vnu * logf(kap * 0.5f + 1e-12f) - lgammaf(vnu + 1.0f);
        } else {
            logI = kap - 0.5f * logf(2.0f * 3.14159265358979323846f * kap + 1e-12f);
        }
        g_logC[i] = -vnu * logf(kap + 1e-12f) - half_d * LOG2PIF - logI;
        float kc = fmaxf(kap, 1e-8f);
        g_A[i] = (kc > 50.0f) ? (1.0f - 127.0f / (2.0f * kc)) : (kc / 128.0f);
    }
}

// ---------------- K2: fused main ----------------
// 256 threads, NB=16 samples per block, 4 groups of 64 k-threads, 4 samples each.
__global__ void __launch_bounds__(256) k_main(const float* __restrict__ feat,
                                              const int* __restrict__ labels32) {
    __shared__ __align__(16) float f[NB][DD];        // 8KB
    __shared__ __align__(16) float musT_sh[DD * KC]; // 32KB
    __shared__ float Lsh[NB][KC];                    // 4KB
    __shared__ float invn[NB];
    __shared__ int lab[NB];
    int tid = threadIdx.x;
    int n0 = blockIdx.x * NB;

    // load 16x128 features as float4 (512 vecs / 256 threads = 2 each)
    {
        const float4* src = (const float4*)(feat + n0 * DD);
        float4* dst = (float4*)&f[0][0];
        dst[tid]       = src[tid];
        dst[tid + 256] = src[tid + 256];
    }
    // copy musT (2048 float4 / 256 threads = 8 each)
    {
        const float4* src = (const float4*)g_musT;
        float4* dst = (float4*)musT_sh;
#pragma unroll
        for (int r = 0; r < 8; r++)
            dst[tid + 256 * r] = src[tid + 256 * r];
    }
    if (tid < NB) {
        int shift = (g_not64 == 0) ? 1 : 0;
        int l = labels32[(n0 + tid) << shift];
        lab[tid] = min(max(l, 0), KC - 1);
    }
    __syncthreads();

    // row norms: warp w handles rows 2w, 2w+1
    int w = tid >> 5, lane = tid & 31;
#pragma unroll
    for (int rr = 0; rr < 2; rr++) {
        int r = 2 * w + rr;
        float s = 0.0f;
#pragma unroll
        for (int c = 0; c < 4; c++) {
            float x = f[r][lane + 32 * c];
            s += x * x;
        }
#pragma unroll
        for (int o = 16; o > 0; o >>= 1) s += __shfl_xor_sync(0xffffffffu, s, o);
        if (lane == 0) invn[r] = 1.0f / fmaxf(sqrtf(s), 1e-12f);
    }
    __syncthreads();

    // class sums: d = tid&127, half handles 8 samples
    {
        int d = tid & 127, half = tid >> 7;
#pragma unroll
        for (int nn = 0; nn < 8; nn++) {
            int n = half * 8 + nn;
            atomicAdd(&g_sums[lab[n] * DD + d], f[n][d] * invn[n]);
        }
    }
    if (tid < NB) atomicAdd(&g_counts[lab[tid]], 1.0f);

    // L = logC[k] + kappa[k] * invn[n] * (f_n . mu_k); 4 samples per thread
    int g = tid >> 6;        // sample group 0..3
    int k = tid & 63;        // class index
    float acc0 = 0.f, acc1 = 0.f, acc2 = 0.f, acc3 = 0.f;
    const float4* f0 = (const float4*)&f[g * 4 + 0][0];
    const float4* f1 = (const float4*)&f[g * 4 + 1][0];
    const float4* f2 = (const float4*)&f[g * 4 + 2][0];
    const float4* f3 = (const float4*)&f[g * 4 + 3][0];
#pragma unroll
    for (int d4 = 0; d4 < DD / 4; d4++) {
        float m0 = musT_sh[(4 * d4 + 0) * KC + k];
        float m1 = musT_sh[(4 * d4 + 1) * KC + k];
        float m2 = musT_sh[(4 * d4 + 2) * KC + k];
        float m3 = musT_sh[(4 * d4 + 3) * KC + k];
        float4 x0 = f0[d4], x1 = f1[d4], x2 = f2[d4], x3 = f3[d4];
        acc0 += m0 * x0.x + m1 * x0.y + m2 * x0.z + m3 * x0.w;
        acc1 += m0 * x1.x + m1 * x1.y + m2 * x1.z + m3 * x1.w;
        acc2 += m0 * x2.x + m1 * x2.y + m2 * x2.z + m3 * x2.w;
        acc3 += m0 * x3.x + m1 * x3.y + m2 * x3.z + m3 * x3.w;
    }
    float kap = g_kappas[k], lc = g_logC[k];
    Lsh[g * 4 + 0][k] = lc + kap * invn[g * 4 + 0] * acc0;
    Lsh[g * 4 + 1][k] = lc + kap * invn[g * 4 + 1] * acc1;
    Lsh[g * 4 + 2][k] = lc + kap * invn[g * 4 + 2] * acc2;
    Lsh[g * 4 + 3][k] = lc + kap * invn[g * 4 + 3] * acc3;
    __syncthreads();

    // numer_pi[label_n][k] += ln2 - softplus(L[n,k] - L[n,label_n])
#pragma unroll
    for (int nn = 0; nn < 4; nn++) {
        int n = g * 4 + nn;
        float Li = Lsh[n][lab[n]];
        float x = Lsh[n][k] - Li;
        float sp = (x > 0.0f) ? (x + log1pf(expf(-x))) : log1pf(expf(x));
        atomicAdd(&g_numer[lab[n] * KC + k], LN2F - sp);
    }
}

// ---------------- K3: rank + js + final combine (self-resetting) ----------------
__global__ void __launch_bounds__(256) k_rankjs(float* __restrict__ out) {
    int i = blockIdx.x;          // row class
    int tid = threadIdx.x;       // 256
    int j = tid & 63;            // col class
    int h4 = tid >> 6;           // d-quarter 0..3
    __shared__ float mean_sh[DD], mui_sh[DD];
    __shared__ float pdm[4][KC], pdu[4][KC];
    __shared__ float dotm_all[KC], dotu_all[KC];
    __shared__ float redr[KC], redj[KC];

    float cnt_i = g_counts[i];
    bool zi = (cnt_i == 0.0f);
    float cs = fmaxf(cnt_i, 1.0f);
    if (tid < DD) {
        float mu = g_mus[i * DD + tid];
        mui_sh[tid] = mu;
        mean_sh[tid] = zi ? mu : (g_sums[i * DD + tid] / cs);
    }
    __syncthreads();

    // each (j, h4) thread: 32-d partial dots, coalesced LDG on musT
    float dm = 0.0f, du = 0.0f;
#pragma unroll
    for (int r = 0; r < 32; r++) {
        int d = h4 * 32 + r;
        float mj = g_musT[d * KC + j];
        dm += mean_sh[d] * mj;
        du += mui_sh[d] * mj;
    }
    pdm[h4][j] = dm;
    pdu[h4][j] = du;
    __syncthreads();
    if (tid < KC) {
        dotm_all[j] = pdm[0][j] + pdm[1][j] + pdm[2][j] + pdm[3][j];
        dotu_all[j] = pdu[0][j] + pdu[1][j] + pdu[2][j] + pdu[3][j];
    }
    __syncthreads();

    if (tid < KC) {
        float dotm = dotm_all[j];
        float dotu = dotu_all[j];
        float diag = dotm_all[i];
        // rank
        float diff = g_kappas[i] * diag - g_kappas[j] * dotm;
        float h = (j != i) ? fmaxf(0.5f * fabsf((float)(i - j)) - diff, 0.0f) / cs : 0.0f;
        // js
        float cnt_j = g_counts[j];
        bool zp = zi || (cnt_j == 0.0f);
        float js;
        if (zp) {
            float ki = g_kappas[i], kj = g_kappas[j];
            js = 0.5f * (g_A[i] * (ki - kj * dotu) + g_A[j] * (kj - ki * dotu));
        } else {
            js = 0.5f * (g_numer[i * KC + j] / cs +
                         g_numer[j * KC + i] / fmaxf(cnt_j, 1.0f));
        }
        float wgt = (i == j) ? 0.0f : fabsf((float)(i - j));
        redr[j] = h;
        redj[j] = wgt * js;
    }
    __syncthreads();
    for (int s = 32; s > 0; s >>= 1) {
        if (tid < s) { redr[tid] += redr[tid + s]; redj[tid] += redj[tid + s]; }
        __syncthreads();
    }
    if (tid == 0) {
        atomicAdd(&g_rank, redr[0]);
        atomicAdd(&g_js, redj[0]);
        __threadfence();
        if (atomicAdd(&g_done, 1) == KC - 1) {
            float r = atomicAdd(&g_rank, 0.0f);   // coherent L2 atomic read
            float s2 = atomicAdd(&g_js, 0.0f);
            out[0] = r / (4096.0f + 1e-9f) + s2 / (87360.0f + 1e-9f);
            // reset for next graph replay
            g_rank = 0.0f; g_js = 0.0f; g_done = 0;
        }
    }
}

extern "C" void kernel_launch(void* const* d_in, const int* in_sizes, int n_in,
                              void* d_out, int out_size) {
    const float* features  = (const float*)d_in[0];
    const float* mus_param = (const float*)d_in[1];
    const float* rho_kappa = (const float*)d_in[2];
    const int*   labels32  = (const int*)d_in[3];
    float* out = (float*)d_out;

    k_prep<<<KC, DD>>>(mus_param, rho_kappa, labels32);
    k_main<<<NN / NB, 256>>>(features, labels32);
    k_rankjs<<<KC, 256>>>(out);
}

// round 5
// speedup vs baseline: 2.0890x; 1.1364x over previous
#include <cuda_runtime.h>
#include <cuda_bf16.h>
#include <math.h>

#define KC 64
#define DD 128
#define NN 4096
#define NB 16
#define MPAD 129   // padded smem row stride for mus: bank(k*129+d) = (k+d)%32 -> conflict-free

#define LN2F 0.6931471805599453f
#define LOG2PIF 1.8378770664093453f      // log(2*pi)
#define LGAMMA64F 201.00931639928152f    // lgamma(64) = ln(63!)

// ---------------- device scratch (statically zero-initialized; self-resetting) ----------------
__device__ float g_sums[KC * DD];     // class sums of normalized features
__device__ float g_counts[KC];
__device__ float g_numer[KC * KC];    // numer_pi
__device__ float g_rank;
__device__ float g_js;
__device__ int   g_done;

// ---------------- helpers ----------------
__device__ __forceinline__ float softplus_precise(float x) {
    return (x > 0.0f) ? (x + log1pf(expf(-x))) : log1pf(expf(x));
}

// ---------------- K1: fused main (prep-per-block + sums + L + numer) ----------------
__global__ void __launch_bounds__(256) k_main(const float* __restrict__ feat,
                                              const float* __restrict__ musp,
                                              const float* __restrict__ rho,
                                              const int* __restrict__ lab32) {
    __shared__ float mus_sh[KC * MPAD];              // 33024 B, raw (unnormalized) mus
    __shared__ __align__(16) float f[NB][DD];        // 8KB raw features
    __shared__ float Lsh[NB][KC];                    // 4KB
    __shared__ float invn[NB];
    __shared__ float invmu[KC], kap_sh[KC], lc_sh[KC];
    __shared__ float musq[4][KC];
    __shared__ int lab[NB];
    int tid = threadIdx.x;
    int n0 = blockIdx.x * NB;

    // labels dtype probe: odd int32 words of first 512 words (nonzero => int32)
    int pred = (lab32[2 * tid + 1] != 0);

    // load mus_param coalesced, scatter into padded rows
    {
        const float4* msrc = (const float4*)musp;
#pragma unroll
        for (int r = 0; r < 8; r++) {
            int idx = tid + 256 * r;          // float4 index; 32 float4 per row
            float4 v = msrc[idx];
            int k = idx >> 5, d = (idx & 31) * 4;
            float* p = &mus_sh[k * MPAD + d];
            p[0] = v.x; p[1] = v.y; p[2] = v.z; p[3] = v.w;
        }
    }
    // load features
    {
        const float4* src = (const float4*)(feat + n0 * DD);
        float4* dst = (float4*)&f[0][0];
        dst[tid]       = src[tid];
        dst[tid + 256] = src[tid + 256];
    }
    int anyodd = __syncthreads_or(pred);     // barrier + block-wide OR

    if (tid < NB) {
        int shift = anyodd ? 0 : 1;
        int l = lab32[(n0 + tid) << shift];
        lab[tid] = min(max(l, 0), KC - 1);
    }

    // mus squared-norm partials: thread (k, quarter)
    {
        int k = tid & 63, q = tid >> 6;
        float s = 0.0f;
#pragma unroll
        for (int r = 0; r < 32; r++) {
            float m = mus_sh[k * MPAD + q * 32 + r];
            s += m * m;
        }
        musq[q][k] = s;
    }
    // feature norms: warp w handles rows 2w, 2w+1
    {
        int w = tid >> 5, lane = tid & 31;
#pragma unroll
        for (int rr = 0; rr < 2; rr++) {
            int r = 2 * w + rr;
            float s = 0.0f;
#pragma unroll
            for (int c = 0; c < 4; c++) {
                float x = f[r][lane + 32 * c];
                s += x * x;
            }
#pragma unroll
            for (int o = 16; o > 0; o >>= 1) s += __shfl_xor_sync(0xffffffffu, s, o);
            if (lane == 0) invn[r] = 1.0f / fmaxf(sqrtf(s), 1e-12f);
        }
    }
    __syncthreads();

    // per-class scalars
    if (tid < KC) {
        float s = musq[0][tid] + musq[1][tid] + musq[2][tid] + musq[3][tid];
        invmu[tid] = 1.0f / fmaxf(sqrtf(s), 1e-12f);
        float r = rho[tid];
        float kap = fmaxf(softplus_precise(r), 1e-6f);
        kap_sh[tid] = kap;
        float logI = (kap < 1e-3f)
                   ? 63.0f * logf(kap * 0.5f + 1e-12f) - LGAMMA64F
                   : kap - 0.5f * logf(6.283185307179586f * kap + 1e-12f);
        lc_sh[tid] = -63.0f * logf(kap + 1e-12f) - 64.0f * LOG2PIF - logI;
    }
    __syncthreads();

    // class sums (normalized features) + counts
    {
        int d = tid & 127, half = tid >> 7;
#pragma unroll
        for (int nn = 0; nn < 8; nn++) {
            int n = half * 8 + nn;
            atomicAdd(&g_sums[lab[n] * DD + d], f[n][d] * invn[n]);
        }
    }
    if (tid < NB) atomicAdd(&g_counts[lab[tid]], 1.0f);

    // L = logC[k] + kappa[k]*invmu[k]*invn[n]*(f_n . mu_raw_k); 4 samples/thread
    int g = tid >> 6;
    int k = tid & 63;
    float acc0 = 0.f, acc1 = 0.f, acc2 = 0.f, acc3 = 0.f;
    const float4* f0 = (const float4*)&f[g * 4 + 0][0];
    const float4* f1 = (const float4*)&f[g * 4 + 1][0];
    const float4* f2 = (const float4*)&f[g * 4 + 2][0];
    const float4* f3 = (const float4*)&f[g * 4 + 3][0];
    const float* mrow = &mus_sh[k * MPAD];
#pragma unroll
    for (int d4 = 0; d4 < DD / 4; d4++) {
        float m0 = mrow[4 * d4 + 0];
        float m1 = mrow[4 * d4 + 1];
        float m2 = mrow[4 * d4 + 2];
        float m3 = mrow[4 * d4 + 3];
        float4 x0 = f0[d4], x1 = f1[d4], x2 = f2[d4], x3 = f3[d4];
        acc0 += m0 * x0.x + m1 * x0.y + m2 * x0.z + m3 * x0.w;
        acc1 += m0 * x1.x + m1 * x1.y + m2 * x1.z + m3 * x1.w;
        acc2 += m0 * x2.x + m1 * x2.y + m2 * x2.z + m3 * x2.w;
        acc3 += m0 * x3.x + m1 * x3.y + m2 * x3.z + m3 * x3.w;
    }
    float sk = kap_sh[k] * invmu[k], lc = lc_sh[k];
    Lsh[g * 4 + 0][k] = lc + sk * invn[g * 4 + 0] * acc0;
    Lsh[g * 4 + 1][k] = lc + sk * invn[g * 4 + 1] * acc1;
    Lsh[g * 4 + 2][k] = lc + sk * invn[g * 4 + 2] * acc2;
    Lsh[g * 4 + 3][k] = lc + sk * invn[g * 4 + 3] * acc3;
    __syncthreads();

    // numer_pi[label_n][k] += ln2 - softplus(L[n,k] - L[n,label_n])
#pragma unroll
    for (int nn = 0; nn < 4; nn++) {
        int n = g * 4 + nn;
        float x = Lsh[n][k] - Lsh[n][lab[n]];
        float sp = __logf(1.0f + __expf(-fabsf(x))) + fmaxf(x, 0.0f);
        atomicAdd(&g_numer[lab[n] * KC + k], LN2F - sp);
    }
}

// ---------------- K2: rank + js + final combine (self-resetting) ----------------
__global__ void __launch_bounds__(256) k_rankjs(const float* __restrict__ musp,
                                                const float* __restrict__ rho,
                                                float* __restrict__ out) {
    __shared__ float mus_sh[KC * MPAD];
    __shared__ float mean_sh[DD];
    __shared__ float invmu[KC], kap_sh[KC], A_sh[KC];
    __shared__ float musq[4][KC];
    __shared__ float pdm[4][KC], pdu[4][KC];
    __shared__ float cnts[KC], numr[KC];
    __shared__ float dotm[KC], dotu[KC];
    __shared__ float redr[KC], redj[KC];
    int tid = threadIdx.x;
    int i = blockIdx.x;

    // load mus (padded) + counts + numer row i
    {
        const float4* msrc = (const float4*)musp;
#pragma unroll
        for (int r = 0; r < 8; r++) {
            int idx = tid + 256 * r;
            float4 v = msrc[idx];
            int k = idx >> 5, d = (idx & 31) * 4;
            float* p = &mus_sh[k * MPAD + d];
            p[0] = v.x; p[1] = v.y; p[2] = v.z; p[3] = v.w;
        }
    }
    if (tid < KC) { cnts[tid] = g_counts[tid]; numr[tid] = g_numer[i * KC + tid]; }
    __syncthreads();

    // mus norm partials
    {
        int k = tid & 63, q = tid >> 6;
        float s = 0.0f;
#pragma unroll
        for (int r = 0; r < 32; r++) {
            float m = mus_sh[k * MPAD + q * 32 + r];
            s += m * m;
        }
        musq[q][k] = s;
    }
    __syncthreads();
    if (tid < KC) {
        float s = musq[0][tid] + musq[1][tid] + musq[2][tid] + musq[3][tid];
        invmu[tid] = 1.0f / fmaxf(sqrtf(s), 1e-12f);
        float r = rho[tid];
        float kap = fmaxf(softplus_precise(r), 1e-6f);
        kap_sh[tid] = kap;
        float kc = fmaxf(kap, 1e-8f);
        A_sh[tid] = (kc > 50.0f) ? (1.0f - 127.0f / (2.0f * kc)) : (kc / 128.0f);
    }
    __syncthreads();

    float cnt_i = cnts[i];
    bool zi = (cnt_i == 0.0f);
    float cs = fmaxf(cnt_i, 1.0f);
    if (tid < DD) {
        float mu_i = mus_sh[i * MPAD + tid] * invmu[i];
        mean_sh[tid] = zi ? mu_i : (g_sums[i * DD + tid] / cs);
    }
    __syncthreads();
    // self-reset: rows consumed by this block only
    if (tid < DD) g_sums[i * DD + tid] = 0.0f;
    if (tid < KC) g_numer[i * KC + tid] = 0.0f;

    // dots: thread (j, quarter) from shared mus
    {
        int j = tid & 63, q = tid >> 6;
        float dm = 0.0f, du = 0.0f;
        const float* mi = &mus_sh[i * MPAD + q * 32];
        const float* mj = &mus_sh[j * MPAD + q * 32];
        const float* me = &mean_sh[q * 32];
#pragma unroll
        for (int r = 0; r < 32; r++) {
            float m = mj[r];
            dm += me[r] * m;
            du += mi[r] * m;
        }
        pdm[q][j] = dm;
        pdu[q][j] = du;
    }
    __syncthreads();
    if (tid < KC) {
        dotm[tid] = (pdm[0][tid] + pdm[1][tid] + pdm[2][tid] + pdm[3][tid]) * invmu[tid];
        dotu[tid] = (pdu[0][tid] + pdu[1][tid] + pdu[2][tid] + pdu[3][tid]) * invmu[i] * invmu[tid];
    }
    __syncthreads();

    if (tid < KC) {
        int j = tid;
        float diag = dotm[i];
        float diff = kap_sh[i] * diag - kap_sh[j] * dotm[j];
        float h = (j != i) ? fmaxf(0.5f * fabsf((float)(i - j)) - diff, 0.0f) / cs : 0.0f;
        float cnt_j = cnts[j];
        bool zp = zi || (cnt_j == 0.0f);
        float wgt = (i == j) ? 0.0f : fabsf((float)(i - j));
        float contrib;
        if (zp) {
            float ki = kap_sh[i], kj = kap_sh[j];
            contrib = wgt * 0.5f * (A_sh[i] * (ki - kj * dotu[j]) + A_sh[j] * (kj - ki * dotu[j]));
        } else {
            // symmetry-folded: full js sum == sum_ij w * numer[i][j] / c_i over non-zero pairs
            contrib = wgt * numr[j] / cs;
        }
        redr[j] = h;
        redj[j] = contrib;
    }
    __syncthreads();
    for (int s = 32; s > 0; s >>= 1) {
        if (tid < s) { redr[tid] += redr[tid + s]; redj[tid] += redj[tid + s]; }
        __syncthreads();
    }
    if (tid == 0) {
        atomicAdd(&g_rank, redr[0]);
        atomicAdd(&g_js, redj[0]);
        __threadfence();
        if (atomicAdd(&g_done, 1) == KC - 1) {
            float r = atomicAdd(&g_rank, 0.0f);
            float s2 = atomicAdd(&g_js, 0.0f);
            out[0] = r / (4096.0f + 1e-9f) + s2 / (87360.0f + 1e-9f);
            // reset shared-by-all state for next replay
            for (int c = 0; c < KC; c++) g_counts[c] = 0.0f;
            g_rank = 0.0f; g_js = 0.0f; g_done = 0;
        }
    }
}

extern "C" void kernel_launch(void* const* d_in, const int* in_sizes, int n_in,
                              void* d_out, int out_size) {
    const float* features  = (const float*)d_in[0];
    const float* mus_param = (const float*)d_in[1];
    const float* rho_kappa = (const float*)d_in[2];
    const int*   labels32  = (const int*)d_in[3];
    float* out = (float*)d_out;

    k_main<<<NN / NB, 256>>>(features, mus_param, rho_kappa, labels32);
    k_rankjs<<<KC, 256>>>(mus_param, rho_kappa, out);
}

// round 6
// speedup vs baseline: 2.0930x; 1.0019x over previous
#include <cuda_runtime.h>
#include <cuda_bf16.h>
#include <math.h>

#define KC 64
#define DD 128
#define NN 4096
#define NB 16
#define MPAD 129   // padded smem row stride: bank(k*129+d) conflict-free both ways

#define LN2F 0.6931471805599453f
#define LOG2PIF 1.8378770664093453f      // log(2*pi)
#define LGAMMA64F 201.00931639928152f    // lgamma(64)

// ---------------- device scratch ----------------
// zero-init + self-resetting accumulators:
__device__ float g_sums[KC * DD];
__device__ float g_counts[KC];
__device__ float g_numer[KC * KC];
__device__ float g_rank;
__device__ float g_js;
__device__ int   g_done;
// published by k_main block 0 (overwritten every run, no reset needed):
__device__ __align__(16) float g_musn[KC * DD];   // normalized mus
__device__ float g_kap[KC];
__device__ float g_A[KC];

__device__ __forceinline__ float softplus_precise(float x) {
    return (x > 0.0f) ? (x + log1pf(expf(-x))) : log1pf(expf(x));
}

// ---------------- K1: fused main ----------------
__global__ void __launch_bounds__(256) k_main(const float* __restrict__ feat,
                                              const float* __restrict__ musp,
                                              const float* __restrict__ rho,
                                              const int* __restrict__ lab32) {
    __shared__ float mus_sh[KC * MPAD];              // raw mus, padded
    __shared__ __align__(16) float f[NB][DD];
    __shared__ float Lsh[NB][KC];
    __shared__ float invn[NB];
    __shared__ float invmu[KC], kap_sh[KC], lc_sh[KC];
    __shared__ float musq[4][KC];
    __shared__ int lab[NB];
    int tid = threadIdx.x;
    int n0 = blockIdx.x * NB;

    // labels dtype probe (odd words nonzero => int32)
    int pred = (lab32[2 * tid + 1] != 0);

    // load mus_param coalesced -> padded rows
    {
        const float4* msrc = (const float4*)musp;
#pragma unroll
        for (int r = 0; r < 8; r++) {
            int idx = tid + 256 * r;
            float4 v = msrc[idx];
            int k = idx >> 5, d = (idx & 31) * 4;
            float* p = &mus_sh[k * MPAD + d];
            p[0] = v.x; p[1] = v.y; p[2] = v.z; p[3] = v.w;
        }
    }
    // load features
    {
        const float4* src = (const float4*)(feat + n0 * DD);
        float4* dst = (float4*)&f[0][0];
        dst[tid]       = src[tid];
        dst[tid + 256] = src[tid + 256];
    }
    int anyodd = __syncthreads_or(pred);

    if (tid < NB) {
        int shift = anyodd ? 0 : 1;
        int l = lab32[(n0 + tid) << shift];
        lab[tid] = min(max(l, 0), KC - 1);
    }

    // mus squared-norm partials
    {
        int k = tid & 63, q = tid >> 6;
        float s = 0.0f;
#pragma unroll
        for (int r = 0; r < 32; r++) {
            float m = mus_sh[k * MPAD + q * 32 + r];
            s += m * m;
        }
        musq[q][k] = s;
    }
    // feature norms
    {
        int w = tid >> 5, lane = tid & 31;
#pragma unroll
        for (int rr = 0; rr < 2; rr++) {
            int r = 2 * w + rr;
            float s = 0.0f;
#pragma unroll
            for (int c = 0; c < 4; c++) {
                float x = f[r][lane + 32 * c];
                s += x * x;
            }
#pragma unroll
            for (int o = 16; o > 0; o >>= 1) s += __shfl_xor_sync(0xffffffffu, s, o);
            if (lane == 0) invn[r] = 1.0f / fmaxf(sqrtf(s), 1e-12f);
        }
    }
    __syncthreads();

    // per-class scalars
    if (tid < KC) {
        float s = musq[0][tid] + musq[1][tid] + musq[2][tid] + musq[3][tid];
        invmu[tid] = 1.0f / fmaxf(sqrtf(s), 1e-12f);
        float r = rho[tid];
        float kap = fmaxf(softplus_precise(r), 1e-6f);
        kap_sh[tid] = kap;
        float logI = (kap < 1e-3f)
                   ? 63.0f * logf(kap * 0.5f + 1e-12f) - LGAMMA64F
                   : kap - 0.5f * logf(6.283185307179586f * kap + 1e-12f);
        lc_sh[tid] = -63.0f * logf(kap + 1e-12f) - 64.0f * LOG2PIF - logI;
    }
    __syncthreads();

    // block 0 publishes normalized mus + kappa + A for k_rankjs
    if (blockIdx.x == 0) {
#pragma unroll
        for (int r = 0; r < 32; r++) {
            int idx = tid + 256 * r;               // 0..8191
            int k = idx >> 7, d = idx & 127;
            g_musn[idx] = mus_sh[k * MPAD + d] * invmu[k];
        }
        if (tid < KC) {
            float kap = kap_sh[tid];
            g_kap[tid] = kap;
            float kc = fmaxf(kap, 1e-8f);
            g_A[tid] = (kc > 50.0f) ? (1.0f - 127.0f / (2.0f * kc)) : (kc / 128.0f);
        }
    }

    // class sums + counts
    {
        int d = tid & 127, half = tid >> 7;
#pragma unroll
        for (int nn = 0; nn < 8; nn++) {
            int n = half * 8 + nn;
            atomicAdd(&g_sums[lab[n] * DD + d], f[n][d] * invn[n]);
        }
    }
    if (tid < NB) atomicAdd(&g_counts[lab[tid]], 1.0f);

    // L = logC + kappa*invmu*invn*(f . mu_raw); 4 samples/thread
    int g = tid >> 6;
    int k = tid & 63;
    float acc0 = 0.f, acc1 = 0.f, acc2 = 0.f, acc3 = 0.f;
    const float4* f0 = (const float4*)&f[g * 4 + 0][0];
    const float4* f1 = (const float4*)&f[g * 4 + 1][0];
    const float4* f2 = (const float4*)&f[g * 4 + 2][0];
    const float4* f3 = (const float4*)&f[g * 4 + 3][0];
    const float* mrow = &mus_sh[k * MPAD];
#pragma unroll
    for (int d4 = 0; d4 < DD / 4; d4++) {
        float m0 = mrow[4 * d4 + 0];
        float m1 = mrow[4 * d4 + 1];
        float m2 = mrow[4 * d4 + 2];
        float m3 = mrow[4 * d4 + 3];
        float4 x0 = f0[d4], x1 = f1[d4], x2 = f2[d4], x3 = f3[d4];
        acc0 += m0 * x0.x + m1 * x0.y + m2 * x0.z + m3 * x0.w;
        acc1 += m0 * x1.x + m1 * x1.y + m2 * x1.z + m3 * x1.w;
        acc2 += m0 * x2.x + m1 * x2.y + m2 * x2.z + m3 * x2.w;
        acc3 += m0 * x3.x + m1 * x3.y + m2 * x3.z + m3 * x3.w;
    }
    float sk = kap_sh[k] * invmu[k], lc = lc_sh[k];
    Lsh[g * 4 + 0][k] = lc + sk * invn[g * 4 + 0] * acc0;
    Lsh[g * 4 + 1][k] = lc + sk * invn[g * 4 + 1] * acc1;
    Lsh[g * 4 + 2][k] = lc + sk * invn[g * 4 + 2] * acc2;
    Lsh[g * 4 + 3][k] = lc + sk * invn[g * 4 + 3] * acc3;
    __syncthreads();

    // numer_pi[label_n][k] += ln2 - softplus(L[n,k] - L[n,label_n])
#pragma unroll
    for (int nn = 0; nn < 4; nn++) {
        int n = g * 4 + nn;
        float x = Lsh[n][k] - Lsh[n][lab[n]];
        float sp = __logf(1.0f + __expf(-fabsf(x))) + fmaxf(x, 0.0f);
        atomicAdd(&g_numer[lab[n] * KC + k], LN2F - sp);
    }
}

// ---------------- K2: rank + js + final combine (lean, self-resetting) ----------------
__global__ void __launch_bounds__(256) k_rankjs(float* __restrict__ out) {
    __shared__ float mus_sh[KC * MPAD];   // normalized mus, padded
    __shared__ float mean_sh[DD];
    __shared__ float pdm[4][KC], pdu[4][KC];
    __shared__ float cnts[KC], numr[KC], kap_s[KC], A_s[KC];
    __shared__ float dotm[KC], dotu[KC];
    __shared__ float redr[KC], redj[KC];
    int tid = threadIdx.x;
    int i = blockIdx.x;

    // load normalized mus (coalesced LDG, scattered to padded rows)
    {
        const float4* msrc = (const float4*)g_musn;
#pragma unroll
        for (int r = 0; r < 8; r++) {
            int idx = tid + 256 * r;
            float4 v = msrc[idx];
            int k = idx >> 5, d = (idx & 31) * 4;
            float* p = &mus_sh[k * MPAD + d];
            p[0] = v.x; p[1] = v.y; p[2] = v.z; p[3] = v.w;
        }
    }
    if (tid < KC) {
        cnts[tid] = g_counts[tid];
        numr[tid] = g_numer[i * KC + tid];
        kap_s[tid] = g_kap[tid];
        A_s[tid] = g_A[tid];
    }
    __syncthreads();

    float cnt_i = cnts[i];
    bool zi = (cnt_i == 0.0f);
    float cs = fmaxf(cnt_i, 1.0f);
    if (tid < DD)
        mean_sh[tid] = zi ? mus_sh[i * MPAD + tid] : (g_sums[i * DD + tid] / cs);
    __syncthreads();
    // self-reset rows consumed only by this block
    if (tid < DD) g_sums[i * DD + tid] = 0.0f;
    if (tid < KC) g_numer[i * KC + tid] = 0.0f;

    // dots: thread (j, quarter)
    {
        int j = tid & 63, q = tid >> 6;
        float dm = 0.0f, du = 0.0f;
        const float* mi = &mus_sh[i * MPAD + q * 32];
        const float* mj = &mus_sh[j * MPAD + q * 32];
        const float* me = &mean_sh[q * 32];
#pragma unroll
        for (int r = 0; r < 32; r++) {
            float m = mj[r];
            dm += me[r] * m;
            du += mi[r] * m;
        }
        pdm[q][j] = dm;
        pdu[q][j] = du;
    }
    __syncthreads();
    if (tid < KC) {
        dotm[tid] = pdm[0][tid] + pdm[1][tid] + pdm[2][tid] + pdm[3][tid];
        dotu[tid] = pdu[0][tid] + pdu[1][tid] + pdu[2][tid] + pdu[3][tid];
    }
    __syncthreads();

    if (tid < KC) {
        int j = tid;
        float diff = kap_s[i] * dotm[i] - kap_s[j] * dotm[j];
        float h = (j != i) ? fmaxf(0.5f * fabsf((float)(i - j)) - diff, 0.0f) / cs : 0.0f;
        float cnt_j = cnts[j];
        bool zp = zi || (cnt_j == 0.0f);
        float wgt = (i == j) ? 0.0f : fabsf((float)(i - j));
        float contrib;
        if (zp) {
            float ki = kap_s[i], kj = kap_s[j];
            contrib = wgt * 0.5f * (A_s[i] * (ki - kj * dotu[j]) + A_s[j] * (kj - ki * dotu[j]));
        } else {
            contrib = wgt * numr[j] / cs;   // symmetry-folded JS
        }
        redr[j] = h;
        redj[j] = contrib;
    }
    __syncthreads();
    // single-warp final reduction
    if (tid < 32) {
        float r = redr[tid] + redr[tid + 32];
        float jj = redj[tid] + redj[tid + 32];
#pragma unroll
        for (int o = 16; o > 0; o >>= 1) {
            r  += __shfl_xor_sync(0xffffffffu, r, o);
            jj += __shfl_xor_sync(0xffffffffu, jj, o);
        }
        if (tid == 0) {
            atomicAdd(&g_rank, r);
            atomicAdd(&g_js, jj);
            __threadfence();
            if (atomicAdd(&g_done, 1) == KC - 1) {
                float rr = atomicAdd(&g_rank, 0.0f);
                float ss = atomicAdd(&g_js, 0.0f);
                out[0] = rr / (4096.0f + 1e-9f) + ss / (87360.0f + 1e-9f);
                for (int c = 0; c < KC; c++) g_counts[c] = 0.0f;
                g_rank = 0.0f; g_js = 0.0f; g_done = 0;
            }
        }
    }
}

extern "C" void kernel_launch(void* const* d_in, const int* in_sizes, int n_in,
                              void* d_out, int out_size) {
    const float* features  = (const float*)d_in[0];
    const float* mus_param = (const float*)d_in[1];
    const float* rho_kappa = (const float*)d_in[2];
    const int*   labels32  = (const int*)d_in[3];
    float* out = (float*)d_out;

    k_main<<<NN / NB, 256>>>(features, mus_param, rho_kappa, labels32);
    k_rankjs<<<KC, 256>>>(out);
}